// round 7
// baseline (speedup 1.0000x reference)
#include <cuda_runtime.h>

// VectorQuantizer forward — round 6: persistent CTAs + 512 threads + FFMA2.
//   z   : [64, 4096, 64] f32  -> 262144 rows x 64 dims
//   emb : [512, 64] f32
// out: [z_q (16777216)] [loss (1)] [indices as float (262144)]
//
// dist_k = (||z||^2 - 2*z.e_k) + ||e_k||^2, argmin, first-index tie-break.
// Dot accumulation order identical to R5 (sequential d, fma.rn.f32x2 halves)
// -> bit-exact indices / z_q.
//
// 148 persistent CTAs, 1/SM. emb loaded+transposed ONCE per CTA. z tiles
// (64 rows) double-buffered in smem, next tile LDG-prefetched during the
// mainloop. 16 warps: warp pair (2w, 2w+1) owns rows 8w..8w+7; even warp
// handles codes [0,256), odd warp codes [256,512); halves merged via smem.

#define NUM_EMB   512
#define EMB_DIM   64
#define ROWS_TILE 64
#define BN        (64 * 4096)          // 262144 rows
#define NTILES    (BN / ROWS_TILE)     // 4096
#define ZQ_ELEMS  (BN * EMB_DIM)       // 16777216
#define EMB_PITCH 514                  // floats (even -> u64 pitch 257)
#define Z2_PITCH  65                   // u64 per (d) row of duplicated z
#define TILE_U64  (EMB_DIM * Z2_PITCH) // u64 elems per z buffer
#define NCTA      148
#define NTHREADS  512

typedef unsigned long long u64;

__device__ double       g_partials[NCTA];
__device__ unsigned int g_count;       // zero-init; reset each launch by last block

__device__ __forceinline__ u64 pack_dup(float v) {
    u64 r; asm("mov.b64 %0, {%1, %1};" : "=l"(r) : "f"(v)); return r;
}
__device__ __forceinline__ void fma2(u64& d, u64 a, u64 b) {
    asm("fma.rn.f32x2 %0, %1, %2, %0;" : "+l"(d) : "l"(a), "l"(b));
}
__device__ __forceinline__ void unpack2(float& lo, float& hi, u64 v) {
    asm("mov.b64 {%0, %1}, %2;" : "=f"(lo), "=f"(hi) : "l"(v));
}

// thread t: row = t>>3 (0..63), holds dims (t&7)*8 .. +7 of that row
__device__ __forceinline__ void ldg_tile(const float* __restrict__ z, int tile,
                                         float4& a, float4& b, int tid) {
    const float4* p = reinterpret_cast<const float4*>(
        z + (size_t)tile * ROWS_TILE * EMB_DIM);
    int row = tid >> 3, q = tid & 7;
    a = p[row * 16 + q * 2];
    b = p[row * 16 + q * 2 + 1];
}

__device__ __forceinline__ void sts_tile(u64* __restrict__ zbuf,
                                         float* __restrict__ znorm,
                                         float4 a, float4 b, int tid) {
    int row = tid >> 3, q = tid & 7, dbase = q * 8;
    float v[8] = {a.x, a.y, a.z, a.w, b.x, b.y, b.z, b.w};
    float s = 0.f;
    #pragma unroll
    for (int i = 0; i < 8; i++) {
        zbuf[(dbase + i) * Z2_PITCH + row] = pack_dup(v[i]);
        s = fmaf(v[i], v[i], s);
    }
    s += __shfl_down_sync(0xffffffffu, s, 4, 8);
    s += __shfl_down_sync(0xffffffffu, s, 2, 8);
    s += __shfl_down_sync(0xffffffffu, s, 1, 8);
    if (q == 0) znorm[row] = s;
}

__global__ __launch_bounds__(NTHREADS, 1)
void vq_main(const float* __restrict__ z, const float* __restrict__ emb,
             float* __restrict__ out, float* __restrict__ idx_out,
             int write_loss)
{
    extern __shared__ char smem_raw[];
    float* emb_s = reinterpret_cast<float*>(smem_raw);               // [64][514]
    u64*   z2    = reinterpret_cast<u64*>(smem_raw +
                       (size_t)EMB_DIM * EMB_PITCH * sizeof(float)); // [2][64][65]
    __shared__ float  enorm_s[NUM_EMB];
    __shared__ float  znorm_s[2][ROWS_TILE];
    __shared__ float  cand_v[ROWS_TILE][2];
    __shared__ int    cand_i[ROWS_TILE][2];
    __shared__ double loss_s[8];
    __shared__ unsigned int is_last_s;
    __shared__ double dsum_s[NTHREADS];

    const int tid   = threadIdx.x;
    const int lane  = tid & 31;
    const int warp  = tid >> 5;          // 0..15
    const int h     = warp & 1;          // code half
    const int rbase = (warp >> 1) * 8;   // 8 rows per warp pair

    // ---- one-time: emb transposed into smem (coalesced) + ||e||^2 ----
    for (int idx = tid; idx < NUM_EMB * EMB_DIM; idx += NTHREADS) {
        int k = idx >> 6, d = idx & 63;
        emb_s[d * EMB_PITCH + k] = emb[idx];
    }
    __syncthreads();
    {   // one code per thread, sequential fmaf chain (same rounding as R5)
        int k = tid;
        if (k < NUM_EMB) {
            float s = 0.f;
            #pragma unroll 8
            for (int d = 0; d < EMB_DIM; d++) {
                float e = emb_s[d * EMB_PITCH + k];
                s = fmaf(e, e, s);
            }
            enorm_s[k] = s;
        }
    }

    // ---- fill first tile into buffer 0 ----
    int tile = blockIdx.x;
    if (tile < NTILES) {
        float4 a, b;
        ldg_tile(z, tile, a, b, tid);
        sts_tile(z2, znorm_s[0], a, b, tid);
    }
    __syncthreads();

    int cur = 0;
    double lsum = 0.0;

    while (tile < NTILES) {
        const int  nxt      = tile + gridDim.x;
        const bool has_next = (nxt < NTILES);
        float4 pa, pb;
        if (has_next) ldg_tile(z, nxt, pa, pb, tid);   // prefetch under mainloop

        // ---- mainloop: 8 rows x 4 code-pairs per thread ----
        u64 acc[32];
        #pragma unroll
        for (int i = 0; i < 32; i++) acc[i] = 0ull;

        const u64* __restrict__ ebase = reinterpret_cast<const u64*>(emb_s)
                                        + h * 128 + lane;
        const u64* __restrict__ zbase = z2 + cur * TILE_U64 + rbase;

        #pragma unroll 2
        for (int d = 0; d < EMB_DIM; d++) {
            u64 zp[8];
            #pragma unroll
            for (int r = 0; r < 8; r++)
                zp[r] = zbase[d * Z2_PITCH + r];       // 8B broadcast LDS
            const u64* ep = ebase + d * (EMB_PITCH / 2);
            #pragma unroll
            for (int jj = 0; jj < 4; jj++) {
                u64 ev = ep[32 * jj];                  // LDS.64 conflict-free
                #pragma unroll
                for (int r = 0; r < 8; r++)
                    fma2(acc[r * 4 + jj], zp[r], ev);
            }
        }

        // ---- epilogue part 1: per-warp argmin over its code half ----
        const u64* enorm_p = reinterpret_cast<const u64*>(enorm_s) + h * 128 + lane;
        #pragma unroll
        for (int r = 0; r < 8; r++) {
            const int row = rbase + r;
            const float zn = znorm_s[cur][row];
            float bv = 3.402823466e38f;
            int   bi = 0x7fffffff;
            #pragma unroll
            for (int jj = 0; jj < 4; jj++) {
                float lo, hi, e0, e1;
                unpack2(lo, hi, acc[r * 4 + jj]);
                unpack2(e0, e1, enorm_p[32 * jj]);     // ||e||^2 pair, LDS.64
                int c0 = h * 256 + 2 * lane + 64 * jj;
                // replicate reference rounding: (||z||^2 - 2*dot) + ||e||^2
                float d0 = __fadd_rn(__fsub_rn(zn, __fmul_rn(2.0f, lo)), e0);
                float d1 = __fadd_rn(__fsub_rn(zn, __fmul_rn(2.0f, hi)), e1);
                if (d0 < bv) { bv = d0; bi = c0; }
                if (d1 < bv) { bv = d1; bi = c0 + 1; }
            }
            #pragma unroll
            for (int off = 16; off; off >>= 1) {
                float ov = __shfl_xor_sync(0xffffffffu, bv, off);
                int   oi = __shfl_xor_sync(0xffffffffu, bi, off);
                if (ov < bv || (ov == bv && oi < bi)) { bv = ov; bi = oi; }
            }
            if (lane == 0) { cand_v[row][h] = bv; cand_i[row][h] = bi; }
        }
        __syncthreads();   // cand ready; prev-iter buffer reads all done

        // ---- epilogue part 2 (even warps): merge halves, write zq/idx ----
        if (h == 0) {
            const float* zcurf = reinterpret_cast<const float*>(z2 + cur * TILE_U64);
            #pragma unroll
            for (int r = 0; r < 8; r++) {
                const int row = rbase + r;
                float v0 = cand_v[row][0], v1 = cand_v[row][1];
                int   i0 = cand_i[row][0], i1 = cand_i[row][1];
                float bv; int bi;
                if (v1 < v0) { bv = v1; bi = i1; }     // tie -> half0 (lower idx)
                else         { bv = v0; bi = i0; }
                const size_t grow = (size_t)tile * ROWS_TILE + row;
                #pragma unroll
                for (int t2 = 0; t2 < 2; t2++) {
                    int d = lane + 32 * t2;
                    float e  = emb_s[d * EMB_PITCH + bi];
                    float zv = zcurf[(d * Z2_PITCH + row) * 2];   // lo half
                    out[grow * EMB_DIM + d] = __fadd_rn(zv, __fsub_rn(e, zv));
                }
                if (lane == 0) {
                    if (idx_out) idx_out[grow] = (float)bi;
                    lsum += (double)bv;    // min dist == ||z - z_q||^2
                }
            }
        }

        if (has_next) sts_tile(z2 + (cur ^ 1) * TILE_U64, znorm_s[cur ^ 1],
                               pa, pb, tid);
        __syncthreads();   // next buffer + znorm ready

        tile = nxt;
        cur ^= 1;
    }

    // ---- loss finalization ----
    if (h == 0 && lane == 0) loss_s[warp >> 1] = lsum;
    __syncthreads();
    if (!write_loss) return;

    if (tid == 0) {
        double s = 0.0;
        #pragma unroll
        for (int w = 0; w < 8; w++) s += loss_s[w];
        g_partials[blockIdx.x] = s;
        __threadfence();
        is_last_s = (atomicAdd(&g_count, 1u) == gridDim.x - 1);
    }
    __syncthreads();
    if (!is_last_s) return;

    double s = 0.0;
    for (int i = tid; i < (int)gridDim.x; i += NTHREADS)
        s += g_partials[i];
    dsum_s[tid] = s;
    __syncthreads();
    #pragma unroll
    for (int k = NTHREADS / 2; k; k >>= 1) {
        if (tid < k) dsum_s[tid] += dsum_s[tid + k];
        __syncthreads();
    }
    if (tid == 0) {
        out[ZQ_ELEMS] = (float)(1.25 * dsum_s[0] /
                                (double)((double)BN * (double)EMB_DIM));
        g_count = 0;   // reset for graph replay
    }
}

extern "C" void kernel_launch(void* const* d_in, const int* in_sizes, int n_in,
                              void* d_out, int out_size)
{
    const float* z   = (const float*)d_in[0];
    const float* emb = (const float*)d_in[1];
    float* out = (float*)d_out;

    const size_t dyn_smem = (size_t)EMB_DIM * EMB_PITCH * sizeof(float)
                          + (size_t)2 * TILE_U64 * sizeof(u64);
    cudaFuncSetAttribute(vq_main, cudaFuncAttributeMaxDynamicSharedMemorySize,
                         (int)dyn_smem);

    // out layout: [z_q (16777216)] [loss (1)] [indices (262144)]
    const bool extras = (out_size >= ZQ_ELEMS + 1 + BN);
    float* idx_out = extras ? (out + ZQ_ELEMS + 1) : nullptr;
    const int write_loss = (out_size > ZQ_ELEMS) ? 1 : 0;

    vq_main<<<NCTA, NTHREADS, dyn_smem>>>(z, emb, out, idx_out, write_loss);
}